// round 16
// baseline (speedup 1.0000x reference)
#include <cuda_runtime.h>
#include <cstdint>

// Problem shape (fixed by the reference)
#define BATCH 64
#define SEQ   8
#define VOCAB 128000

// 2 splits/row -> 128 blocks x 1024 threads (32 warps/SM, one exact wave).
// Split = 64000 floats = 16000 float4 -> 15 f4/thread + 640-f4 remainder.
#define SPLITS       2
#define THREADS      1024
#define SPLIT_FLOATS (VOCAB / SPLITS)        // 64000
#define SPLIT_F4     (SPLIT_FLOATS / 4)      // 16000

// Scratch (no cudaMalloc allowed). g_count starts 0, reset by last arriver
// each run -> deterministic across graph replays.
__device__ float g_pmax[BATCH * SPLITS];
__device__ int   g_pidx[BATCH * SPLITS];
__device__ int   g_count[BATCH];

__device__ __forceinline__ void take_better(float v, int i, float& bm, int& bi) {
    // full tie-break (first occurrence = smaller index) for cross-thread merge
    if (v > bm || (v == bm && i < bi)) { bm = v; bi = i; }
}

// In-thread scan: this thread's indices strictly increase -> strict > keeps
// first occurrence. fmaxf tree for ILP; index recovered on rare update.
__device__ __forceinline__ void proc(float4 v, int e, float& bm, int& bi) {
    float m = fmaxf(fmaxf(v.x, v.y), fmaxf(v.z, v.w));
    if (m > bm) {
        bm = m;
        bi = (m == v.x) ? e : (m == v.y) ? e + 1 : (m == v.z) ? e + 2 : e + 3;
    }
}

__global__ __launch_bounds__(THREADS, 1) void argmax_wide(
    const float* __restrict__ logits, float* __restrict__ out)
{
    const int row   = blockIdx.x >> 1;      // 0..63
    const int split = blockIdx.x & 1;       // 0..1

    const float4* __restrict__ p = reinterpret_cast<const float4*>(
        logits + (size_t)row * (SEQ * VOCAB) + (size_t)(SEQ - 1) * VOCAB
               + (size_t)split * SPLIT_FLOATS);

    const int tid = threadIdx.x;
    const int idx_base = split * SPLIT_FLOATS;

    float bm = -__int_as_float(0x7f800000);  // -inf
    int   bi = 0x7fffffff;

    // 15 f4/thread as batches of 8 + 7: 8 LDG.128 issued back-to-back per
    // thread, 32 warps/SM -> ~1000 outstanding 128B lines per SM.
    float4 buf[8];
    #pragma unroll
    for (int u = 0; u < 8; ++u) buf[u] = p[tid + u * THREADS];
    #pragma unroll
    for (int u = 0; u < 8; ++u)
        proc(buf[u], idx_base + (tid + u * THREADS) * 4, bm, bi);

    #pragma unroll
    for (int u = 0; u < 7; ++u) buf[u] = p[tid + (8 + u) * THREADS];
    #pragma unroll
    for (int u = 0; u < 7; ++u)
        proc(buf[u], idx_base + (tid + (8 + u) * THREADS) * 4, bm, bi);

    // remainder: 16000 - 15*1024 = 640 f4; first 640 threads take one each
    if (tid < SPLIT_F4 - 15 * THREADS) {
        float4 v = p[tid + 15 * THREADS];
        proc(v, idx_base + (tid + 15 * THREADS) * 4, bm, bi);
    }

    // intra-warp reduce (full tie-break)
    #pragma unroll
    for (int off = 16; off > 0; off >>= 1) {
        float om = __shfl_down_sync(0xffffffffu, bm, off);
        int   oi = __shfl_down_sync(0xffffffffu, bi, off);
        take_better(om, oi, bm, bi);
    }

    __shared__ float sm[THREADS / 32];  // 32 warps
    __shared__ int   si[THREADS / 32];
    const int lane = tid & 31, warp = tid >> 5;
    if (lane == 0) { sm[warp] = bm; si[warp] = bi; }
    __syncthreads();

    if (warp == 0) {
        bm = sm[lane];   // exactly 32 warps -> all lanes valid
        bi = si[lane];
        #pragma unroll
        for (int off = 16; off > 0; off >>= 1) {
            float om = __shfl_down_sync(0xffffffffu, bm, off);
            int   oi = __shfl_down_sync(0xffffffffu, bi, off);
            take_better(om, oi, bm, bi);
        }
        if (lane == 0) {
            // publish this split's partial
            g_pmax[row * SPLITS + split] = bm;
            g_pidx[row * SPLITS + split] = bi;
            __threadfence();
            int old = atomicAdd(&g_count[row], 1);
            if (old == SPLITS - 1) {
                volatile float* vm = g_pmax + row * SPLITS;
                volatile int*   vi = g_pidx + row * SPLITS;
                float fm = vm[0];
                int   fi = vi[0];
                float v1 = vm[1];
                int   i1 = vi[1];
                // split 0 has smaller indices: strict > keeps first occurrence
                if (v1 > fm) { fm = v1; fi = i1; }
                out[row] = (float)fi;   // harness compares as float32
                g_count[row] = 0;       // reset for next graph replay
            }
        }
    }
}

extern "C" void kernel_launch(void* const* d_in, const int* in_sizes, int n_in,
                              void* d_out, int out_size) {
    const float* logits = (const float*)d_in[0];
    argmax_wide<<<BATCH * SPLITS, THREADS>>>(logits, (float*)d_out);
}

// round 17
// speedup vs baseline: 1.1637x; 1.1637x over previous
#include <cuda_runtime.h>
#include <cstdint>

// Problem shape (fixed by the reference)
#define BATCH 64
#define SEQ   8
#define VOCAB 128000

// 5 splits/row -> 320 blocks x 256 threads (8 warps).
// Split = 25600 floats = 6400 float4 -> exactly 25 f4/thread = 5 batches of 5.
#define SPLITS       5
#define THREADS      256
#define SPLIT_FLOATS (VOCAB / SPLITS)        // 25600
#define BATCHES      5
#define BW_          5                        // f4 per batch per thread

// Scratch (no cudaMalloc allowed). g_count starts 0, reset by last arriver
// each run -> deterministic across graph replays.
__device__ float g_pmax[BATCH * SPLITS];
__device__ int   g_pidx[BATCH * SPLITS];
__device__ int   g_count[BATCH];

__device__ __forceinline__ void take_better(float v, int i, float& bm, int& bi) {
    // full tie-break (first occurrence = smaller index) for cross-thread merge
    if (v > bm || (v == bm && i < bi)) { bm = v; bi = i; }
}

__global__ __launch_bounds__(THREADS, 5) void argmax_diet(
    const float* __restrict__ logits, float* __restrict__ out)
{
    const int row   = blockIdx.x / SPLITS;   // 0..63
    const int split = blockIdx.x % SPLITS;   // 0..4

    const float4* __restrict__ p = reinterpret_cast<const float4*>(
        logits + (size_t)row * (SEQ * VOCAB) + (size_t)(SEQ - 1) * VOCAB
               + (size_t)split * SPLIT_FLOATS);

    const int tid = threadIdx.x;
    const int idx_base = split * SPLIT_FLOATS;

    float bm = -__int_as_float(0x7f800000);  // -inf
    int   bi = 0x7fffffff;

    // 5 batches x 5 float4. Inner loop is a pure FMNMX tree (no serial dep,
    // no per-element compare); ONE compare+rare branch per 20-value batch.
    float4 buf[BW_];
    #pragma unroll
    for (int b = 0; b < BATCHES; ++b) {
        #pragma unroll
        for (int u = 0; u < BW_; ++u)
            buf[u] = p[tid + (b * BW_ + u) * THREADS];

        // 20-value max tree: 15 + 4 FMNMX, fully parallel
        float t0 = fmaxf(fmaxf(buf[0].x, buf[0].y), fmaxf(buf[0].z, buf[0].w));
        float t1 = fmaxf(fmaxf(buf[1].x, buf[1].y), fmaxf(buf[1].z, buf[1].w));
        float t2 = fmaxf(fmaxf(buf[2].x, buf[2].y), fmaxf(buf[2].z, buf[2].w));
        float t3 = fmaxf(fmaxf(buf[3].x, buf[3].y), fmaxf(buf[3].z, buf[3].w));
        float t4 = fmaxf(fmaxf(buf[4].x, buf[4].y), fmaxf(buf[4].z, buf[4].w));
        float batchmax = fmaxf(fmaxf(fmaxf(t0, t1), fmaxf(t2, t3)), t4);

        if (batchmax > bm) {   // rare: ~H(5)~2.3 times per thread total
            bm = batchmax;
            // first occurrence within batch = minimum matching index
            int cand = 0x7fffffff;
            #pragma unroll
            for (int u = 0; u < BW_; ++u) {
                const int e = idx_base + (tid + (b * BW_ + u) * THREADS) * 4;
                if (buf[u].w == batchmax) cand = min(cand, e + 3);
                if (buf[u].z == batchmax) cand = min(cand, e + 2);
                if (buf[u].y == batchmax) cand = min(cand, e + 1);
                if (buf[u].x == batchmax) cand = min(cand, e + 0);
            }
            bi = cand;
        }
    }

    // intra-warp reduce (full tie-break)
    #pragma unroll
    for (int off = 16; off > 0; off >>= 1) {
        float om = __shfl_down_sync(0xffffffffu, bm, off);
        int   oi = __shfl_down_sync(0xffffffffu, bi, off);
        take_better(om, oi, bm, bi);
    }

    __shared__ float sm[THREADS / 32];  // 8 warps
    __shared__ int   si[THREADS / 32];
    const int lane = tid & 31, warp = tid >> 5;
    if (lane == 0) { sm[warp] = bm; si[warp] = bi; }
    __syncthreads();

    if (warp == 0) {
        bm = (lane < THREADS / 32) ? sm[lane] : -__int_as_float(0x7f800000);
        bi = (lane < THREADS / 32) ? si[lane] : 0x7fffffff;
        #pragma unroll
        for (int off = 4; off > 0; off >>= 1) {
            float om = __shfl_down_sync(0xffffffffu, bm, off);
            int   oi = __shfl_down_sync(0xffffffffu, bi, off);
            take_better(om, oi, bm, bi);
        }
        if (lane == 0) {
            // publish this split's partial
            g_pmax[row * SPLITS + split] = bm;
            g_pidx[row * SPLITS + split] = bi;
            __threadfence();
            int old = atomicAdd(&g_count[row], 1);
            if (old == SPLITS - 1) {
                // last arriver merges (ascending split order: strict > keeps
                // first occurrence on exact ties)
                volatile float* vm = g_pmax + row * SPLITS;
                volatile int*   vi = g_pidx + row * SPLITS;
                float fm = vm[0];
                int   fi = vi[0];
                #pragma unroll
                for (int s = 1; s < SPLITS; ++s) {
                    float v = vm[s];
                    int   i = vi[s];
                    if (v > fm) { fm = v; fi = i; }
                }
                out[row] = (float)fi;   // harness compares as float32
                g_count[row] = 0;       // reset for next graph replay
            }
        }
    }
}

extern "C" void kernel_launch(void* const* d_in, const int* in_sizes, int n_in,
                              void* d_out, int out_size) {
    const float* logits = (const float*)d_in[0];
    argmax_diet<<<BATCH * SPLITS, THREADS>>>(logits, (float*)d_out);
}